// round 14
// baseline (speedup 1.0000x reference)
#include <cuda_runtime.h>

#define N 96
#define NPAD 97
#define NUM_ITERS 6            // worst-case (λ2/λ1)^6 ~ 4e-5 even for extreme λ2=10; gate is 1e-3
#define NMAT (N * N)           // 9216 matrices
#define MAT_ELEMS (N * N)      // 9216 elements per matrix
#define RESCALE 0.015625f      // 1/64: keeps |b| bounded; ratio b[k]/b[s] is scale-invariant
#define CHUNK 16               // matrices per CTA; grid 576 <= 592 resident -> SINGLE WAVE
#define NCTA (NMAT / CHUNK)    // 576
#define QSG 4                  // load-steps per iteration group (24 steps / 6 iters)

// Per-CTA partial sums, laid out [k][cta]; summed by the last CTA (fixed order).
__device__ float g_scratch[N * NCTA];
__device__ int   g_done;       // zero-init; self-resetting arrival counter (graph-replay safe)

__device__ __forceinline__ float4 sig4(float4 z, float4 c, float4 w) {
    float4 o;
    o.x = 1.f / (1.f + __expf(-fmaf(w.x, z.x, c.x)));
    o.y = 1.f / (1.f + __expf(-fmaf(w.y, z.y, c.y)));
    o.z = 1.f / (1.f + __expf(-fmaf(w.z, z.z, c.z)));
    o.w = 1.f / (1.f + __expf(-fmaf(w.w, z.w, c.w)));
    return o;
}

__global__ __launch_bounds__(N, 4)
void rbc_power_iter_kernel(const float* __restrict__ r_zeros,
                           const float* __restrict__ r_const,
                           const float* __restrict__ weights_r,
                           const float* __restrict__ weights_t,
                           float* __restrict__ out) {
    // SINGLE A buffer: sA is fully consumed by the register row-cache at matrix
    // start, so next matrix stages into the SAME buffer during iterations.
    __shared__ float sA[N * NPAD];                 // 37.9KB -> occupancy 4
    __shared__ __align__(16) float sb[2 * N];      // ping-pong b vector
    __shared__ int s_last;

    const int tid  = threadIdx.x;
    const int m0   = blockIdx.x * CHUNK;
    const int tdiv = tid / 24;                     // staging coords: step k -> row 4k+tdiv, col tj
    const int tj   = 4 * (tid - tdiv * 24);

    // ---- Prologue: fully load matrix m0 (once per CTA, single wave) ----
    {
        const long long base = (long long)m0 * MAT_ELEMS;
        const float4* rz4 = (const float4*)(r_zeros   + base);
        const float4* rc4 = (const float4*)(r_const   + base);
        const float4* wr4 = (const float4*)(weights_r + base);
        #pragma unroll 4
        for (int k = 0; k < 24; ++k) {
            int q = tid + k * N;
            float4 o = sig4(rz4[q], rc4[q], wr4[q]);
            float* dst = &sA[(4 * k + tdiv) * NPAD + tj];
            dst[0] = o.x; dst[1] = o.y; dst[2] = o.z; dst[3] = o.w;
        }
    }
    __syncthreads();

    float ctasum = 0.f;                            // thread tid owns output index k=tid

    #pragma unroll 1
    for (int c = 0; c < CHUNK; ++c) {
        const int m = m0 + c;

        // ---- row-cache: after this sync, sA is dead and reusable ----
        float a[N];
        {
            const float* row = &sA[tid * NPAD];
            #pragma unroll
            for (int j = 0; j < N; ++j) a[j] = row[j];
        }
        sb[tid] = 1.0f;
        __syncthreads();

        const bool pf = (c + 1 < CHUNK);
        const long long nbase = (long long)(m + 1) * MAT_ELEMS;
        const float4* rz4 = (const float4*)(r_zeros   + nbase);
        const float4* rc4 = (const float4*)(r_const   + nbase);
        const float4* wr4 = (const float4*)(weights_r + nbase);

        float4 pz[QSG], pc[QSG], pw[QSG];          // one in-flight load group (48 regs)

        float bi = 1.0f;
        #pragma unroll 1
        for (int it = 0; it < NUM_ITERS; ++it) {
            // consume group issued at it-1 (one full iteration of latency elapsed)
            if (pf && it > 0) {
                const int k0 = QSG * (it - 1);
                #pragma unroll
                for (int u = 0; u < QSG; ++u) {
                    float4 o = sig4(pz[u], pc[u], pw[u]);
                    float* dst = &sA[(4 * (k0 + u) + tdiv) * NPAD + tj];
                    dst[0] = o.x; dst[1] = o.y; dst[2] = o.z; dst[3] = o.w;
                }
            }
            // issue this iteration's group: lands during matvec + next matvec
            if (pf) {
                #pragma unroll
                for (int u = 0; u < QSG; ++u) {
                    int q = tid + (QSG * it + u) * N;
                    pz[u] = rz4[q]; pc[u] = rc4[q]; pw[u] = wr4[q];
                }
            }
            // matvec: register row x broadcast b, 4-way ILP
            const float4* bv4 = (const float4*)&sb[(it & 1) * N];
            float acc0 = 0.f, acc1 = 0.f, acc2 = 0.f, acc3 = 0.f;
            #pragma unroll
            for (int j = 0; j < N; j += 4) {
                float4 bv = bv4[j >> 2];
                acc0 = fmaf(a[j    ], bv.x, acc0);
                acc1 = fmaf(a[j + 1], bv.y, acc1);
                acc2 = fmaf(a[j + 2], bv.z, acc2);
                acc3 = fmaf(a[j + 3], bv.w, acc3);
            }
            bi = ((acc0 + acc1) + (acc2 + acc3)) * RESCALE;
            sb[((it & 1) ^ 1) * N + tid] = bi;
            __syncthreads();
        }

        // tail: consume the last group (issued at it = NUM_ITERS-1)
        if (pf) {
            const int k0 = QSG * (NUM_ITERS - 1);
            #pragma unroll
            for (int u = 0; u < QSG; ++u) {
                float4 o = sig4(pz[u], pc[u], pw[u]);
                float* dst = &sA[(4 * (k0 + u) + tdiv) * NPAD + tj];
                dst[0] = o.x; dst[1] = o.y; dst[2] = o.z; dst[3] = o.w;
            }
        }

        // ---- accumulate contribution[k=tid] = wt[s,t] * b[k] / b[s] (scale cancels) ----
        // NUM_ITERS even -> final b lives in sb[0..N)
        const int s = m / N;
        const float b_s = sb[s];
        ctasum = fmaf(bi / b_s, weights_t[m], ctasum);
        __syncthreads();                           // sb + sA safe before next matrix
    }

    g_scratch[tid * NCTA + blockIdx.x] = ctasum;   // one coalesced write per CTA

    // ---- last-CTA deterministic reduction (fixed order: cta 0..575 per k) ----
    __threadfence();
    if (tid == 0) {
        int prev = atomicAdd(&g_done, 1);
        s_last = (prev == NCTA - 1) ? 1 : 0;
    }
    __syncthreads();
    if (s_last) {
        __threadfence();                           // acquire: all CTAs' partials visible
        const float4* row4 = (const float4*)&g_scratch[tid * NCTA];
        float s = 0.f;
        #pragma unroll 8
        for (int i = 0; i < NCTA / 4; ++i) {       // 144 float4s, L2-resident
            float4 v = row4[i];
            s += (v.x + v.y) + (v.z + v.w);
        }
        out[tid] = s;
        if (tid == 0) g_done = 0;                  // reset for next graph replay
    }
}

extern "C" void kernel_launch(void* const* d_in, const int* in_sizes, int n_in,
                              void* d_out, int out_size) {
    // metadata order: x, r_zeros, r_const, max_error, weights_t, weights_r
    const float* r_zeros   = (const float*)d_in[1];
    const float* r_const   = (const float*)d_in[2];
    const float* weights_t = (const float*)d_in[4];
    const float* weights_r = (const float*)d_in[5];
    float* out = (float*)d_out;

    rbc_power_iter_kernel<<<NCTA, N>>>(r_zeros, r_const, weights_r, weights_t, out);
}